// round 9
// baseline (speedup 1.0000x reference)
#include <cuda_runtime.h>
#include <cstdint>

#define N_TOK   4096
#define C_DIM   64
#define HW      256
#define E_EXP   16
#define CCAP    384
#define PLANE   (E_EXP * CCAP)             /* 6144 */
#define HALF    ((long long)N_TOK * PLANE) /* 25,165,824 floats */

// ---------------- device scratch (reset each replay by finish block) ----------------
__device__ float g_gate[N_TOK];
__device__ int   g_arg[N_TOK];
__device__ float g_psum[E_EXP];
__device__ float g_zsum;
__device__ int   g_chunk[16];     // tokens completed per 256-token chunk

// =====================================================================
// K1: pure-read pool + embedded finish. grid = 4097 x 512.
//   bid < 4096 : pool token bid (64KB streaming read), signal chunk counter
//   bid == 4096: finish — per-warp incremental scan, scatter, scalars, reset
// Runs after the driver memset node (stream-ordered), so scatter is safe.
// =====================================================================
__global__ void __launch_bounds__(512, 4)
k_pool(const float* __restrict__ X, const float* __restrict__ Wg,
       const float* __restrict__ bg, float* __restrict__ out) {
    const int bid  = blockIdx.x;
    const int tid  = threadIdx.x;
    const int w    = tid >> 5;
    const int lane = tid & 31;

    if (bid < N_TOK) {
        const int n = bid;
        __shared__ float s_ch[C_DIM];
        __shared__ float s_w[C_DIM * E_EXP];

        for (int i = tid; i < C_DIM * E_EXP; i += 512) s_w[i] = Wg[i];

        // coalesced streaming read; warp w owns channels [4w, 4w+4)
        const float4* p = reinterpret_cast<const float4*>(X + (size_t)n * C_DIM * HW)
                          + w * 256;
        float part[4] = {0.f, 0.f, 0.f, 0.f};
#pragma unroll
        for (int k = 0; k < 8; k++) {
            float4 v = __ldcs(p + lane + 32 * k);   // lanes consecutive -> coalesced
            part[k >> 1] += (v.x + v.y) + (v.z + v.w);
        }
#pragma unroll
        for (int c = 0; c < 4; c++) {
            float s = part[c];
#pragma unroll
            for (int off = 16; off; off >>= 1) s += __shfl_xor_sync(0xffffffffu, s, off);
            if (lane == 0) s_ch[4 * w + c] = s * (1.0f / HW);
        }
        __syncthreads();

        if (w == 0) {
            float l = -INFINITY;
            if (lane < E_EXP) {
                float acc = bg[lane];
#pragma unroll
                for (int c = 0; c < C_DIM; c++) acc += s_ch[c] * s_w[c * E_EXP + lane];
                l = acc;
            }
            float mx = l;
#pragma unroll
            for (int off = 16; off; off >>= 1) mx = fmaxf(mx, __shfl_xor_sync(0xffffffffu, mx, off));
            float e = (lane < E_EXP) ? __expf(l - mx) : 0.f;
            float s = e;
#pragma unroll
            for (int off = 16; off; off >>= 1) s += __shfl_xor_sync(0xffffffffu, s, off);
            float prob = e / s;
            float lse  = mx + __logf(s);

            unsigned bal = __ballot_sync(0xffffffffu, l == mx);
            int arg = __ffs(bal) - 1;               // lowest-index max == jnp argmax
            float gate = __shfl_sync(0xffffffffu, prob, arg);

            if (lane < E_EXP) atomicAdd(&g_psum[lane], prob);
            if (lane == 0) {
                g_gate[n] = gate;
                g_arg[n]  = arg;
                atomicAdd(&g_zsum, lse);
                __threadfence();
                atomicAdd(&g_chunk[n >> 8], 1);     // chunk readiness signal
            }
        }
        return;
    }

    // ---------------- finish block (bid == 4096) ----------------
    __shared__ unsigned short s_rank[N_TOK];
    __shared__ unsigned char  s_argc[N_TOK];
    __shared__ int s_cnt[16][E_EXP + 1];
    __shared__ int s_off[16][E_EXP + 1];
    __shared__ int s_tot[E_EXP];

    // phase A: warp w waits for chunk w then ranks its 256 tokens (incremental)
    if (lane == 0) {
        while (atomicAdd(&g_chunk[w], 0) < 256) __nanosleep(32);
        __threadfence();
    }
    __syncwarp();

    if (lane <= E_EXP) s_cnt[w][lane] = 0;
    __syncwarp();
#pragma unroll
    for (int g = 0; g < 8; g++) {
        int n = 256 * w + 32 * g + lane;
        int a = g_arg[n];
        unsigned m = __match_any_sync(0xffffffffu, a);
        int prior = s_cnt[w][a];
        __syncwarp();
        if (lane == (int)__ffs(m) - 1) s_cnt[w][a] = prior + __popc(m);
        s_rank[n] = (unsigned short)(prior + __popc(m & ((1u << lane) - 1u)));
        s_argc[n] = (unsigned char)a;
        __syncwarp();
    }
    __syncthreads();

    // phase B: exclusive prefix over 16 chunks (warp w<16 = expert w)
    if (lane < 16) {
        int v = s_cnt[lane][w];
        int x = v;
#pragma unroll
        for (int off = 1; off < 16; off <<= 1) {
            int y = __shfl_up_sync(0x0000ffffu, x, off);
            if (lane >= off) x += y;
        }
        s_off[lane][w] = x - v;
        if (lane == 15) s_tot[w] = x;
    }
    __syncthreads();

    // phase C: positions + scatter nonzeros (memset node already completed)
#pragma unroll
    for (int rep = 0; rep < 8; rep++) {
        int n = tid + rep * 512;
        int a = s_argc[n];
        int pos = s_off[n >> 8][a] + (int)s_rank[n];
        if (pos < CCAP) {
            long long off = (long long)n * PLANE + a * CCAP + pos;
            __stcs(out + off, 1.0f);              // dispatch
            __stcs(out + HALF + off, g_gate[n]);  // combine
        }
    }

    // scalars + state reset for next graph replay
    if (tid == 0) {
        float aux = 0.f;
#pragma unroll
        for (int e = 0; e < E_EXP; e++) aux += g_psum[e] * (float)s_tot[e];
        const float invN = 1.0f / (float)N_TOK;
        out[2 * HALF]     = g_zsum * invN;                       // z_loss
        out[2 * HALF + 1] = aux * (float)E_EXP * invN * invN;    // aux_loss
        g_zsum = 0.f;
#pragma unroll
        for (int e = 0; e < E_EXP; e++) g_psum[e] = 0.f;
        __threadfence();
#pragma unroll
        for (int c = 0; c < 16; c++) g_chunk[c] = 0;
    }
}

// ---------------- launch ----------------
extern "C" void kernel_launch(void* const* d_in, const int* in_sizes, int n_in,
                              void* d_out, int out_size) {
    const float* X  = (const float*)d_in[0];
    const float* Wg = (const float*)d_in[1];
    const float* bg = (const float*)d_in[2];
    float* out = (float*)d_out;

    // driver memset node: pure-write zero-fill of both output planes
    cudaMemsetAsync(out, 0, (size_t)(2 * HALF) * sizeof(float));

    k_pool<<<N_TOK + 1, 512>>>(X, Wg, bg, out);   // pure-read + embedded finish
}

// round 10
// speedup vs baseline: 1.0184x; 1.0184x over previous
#include <cuda_runtime.h>
#include <cstdint>

#define N_TOK   4096
#define C_DIM   64
#define HW      256
#define E_EXP   16
#define CCAP    384
#define PLANE   (E_EXP * CCAP)             /* 6144 */
#define HALF    ((long long)N_TOK * PLANE) /* 25,165,824 floats */

// ---------------- device scratch (reset each replay by the finisher) ----------------
__device__ float g_gate[N_TOK];
__device__ int   g_arg[N_TOK];
__device__ float g_psum[E_EXP];
__device__ float g_zsum;
__device__ int   g_done;          // completed pool blocks

// =====================================================================
// K1: pure-read pool; the LAST block to finish becomes the finisher.
// grid = 4096 x 512. Runs after the driver memset node (stream-ordered).
// =====================================================================
__global__ void __launch_bounds__(512, 4)
k_pool(const float* __restrict__ X, const float* __restrict__ Wg,
       const float* __restrict__ bg, float* __restrict__ out) {
    const int n    = blockIdx.x;
    const int tid  = threadIdx.x;
    const int w    = tid >> 5;
    const int lane = tid & 31;

    __shared__ float s_ch[C_DIM];
    __shared__ float s_w[C_DIM * E_EXP];
    __shared__ int   s_last;

    for (int i = tid; i < C_DIM * E_EXP; i += 512) s_w[i] = Wg[i];

    // coalesced streaming read; warp w owns channels [4w, 4w+4)
    const float4* p = reinterpret_cast<const float4*>(X + (size_t)n * C_DIM * HW)
                      + w * 256;
    float part[4] = {0.f, 0.f, 0.f, 0.f};
#pragma unroll
    for (int k = 0; k < 8; k++) {
        float4 v = __ldcs(p + lane + 32 * k);       // lanes consecutive -> coalesced
        part[k >> 1] += (v.x + v.y) + (v.z + v.w);
    }
#pragma unroll
    for (int c = 0; c < 4; c++) {
        float s = part[c];
#pragma unroll
        for (int off = 16; off; off >>= 1) s += __shfl_xor_sync(0xffffffffu, s, off);
        if (lane == 0) s_ch[4 * w + c] = s * (1.0f / HW);
    }
    __syncthreads();

    if (w == 0) {
        float l = -INFINITY;
        if (lane < E_EXP) {
            float acc = bg[lane];
#pragma unroll
            for (int c = 0; c < C_DIM; c++) acc += s_ch[c] * s_w[c * E_EXP + lane];
            l = acc;
        }
        float mx = l;
#pragma unroll
        for (int off = 16; off; off >>= 1) mx = fmaxf(mx, __shfl_xor_sync(0xffffffffu, mx, off));
        float e = (lane < E_EXP) ? __expf(l - mx) : 0.f;
        float s = e;
#pragma unroll
        for (int off = 16; off; off >>= 1) s += __shfl_xor_sync(0xffffffffu, s, off);
        float prob = e / s;
        float lse  = mx + __logf(s);

        unsigned bal = __ballot_sync(0xffffffffu, l == mx);
        int arg = __ffs(bal) - 1;                   // lowest-index max == jnp argmax
        float gate = __shfl_sync(0xffffffffu, prob, arg);

        if (lane < E_EXP) atomicAdd(&g_psum[lane], prob);
        if (lane == 0) {
            g_gate[n] = gate;
            g_arg[n]  = arg;
            atomicAdd(&g_zsum, lse);
            __threadfence();                        // release all token-n writes
            int old = atomicAdd(&g_done, 1);
            s_last = (old == N_TOK - 1);            // am I the last block?
        }
    }
    __syncthreads();
    if (!s_last) return;

    // ================= finisher (exactly one block, warm SM, hot L2) ==========
    __shared__ unsigned short s_rank[N_TOK];
    __shared__ unsigned char  s_argc[N_TOK];
    __shared__ int s_cnt[16][E_EXP + 1];
    __shared__ int s_off[16][E_EXP + 1];
    __shared__ int s_tot[E_EXP];

    __threadfence();                                // acquire side
    __syncthreads();

    // phase A: per-chunk expert ranks (warp w owns tokens [256w, 256w+256))
    if (lane <= E_EXP) s_cnt[w][lane] = 0;
    __syncwarp();
#pragma unroll
    for (int g = 0; g < 8; g++) {
        int t = 256 * w + 32 * g + lane;
        int a = g_arg[t];
        unsigned m = __match_any_sync(0xffffffffu, a);
        int prior = s_cnt[w][a];
        __syncwarp();
        if (lane == (int)__ffs(m) - 1) s_cnt[w][a] = prior + __popc(m);
        s_rank[t] = (unsigned short)(prior + __popc(m & ((1u << lane) - 1u)));
        s_argc[t] = (unsigned char)a;
        __syncwarp();
    }
    __syncthreads();

    // phase B: exclusive prefix over 16 chunks (warp w = expert w)
    if (lane < 16) {
        int v = s_cnt[lane][w];
        int x = v;
#pragma unroll
        for (int off = 1; off < 16; off <<= 1) {
            int y = __shfl_up_sync(0x0000ffffu, x, off);
            if (lane >= off) x += y;
        }
        s_off[lane][w] = x - v;
        if (lane == 15) s_tot[w] = x;
    }
    __syncthreads();

    // phase C: positions + scatter nonzeros (memset node completed before kernel)
#pragma unroll
    for (int rep = 0; rep < 8; rep++) {
        int t = tid + rep * 512;
        int a = s_argc[t];
        int pos = s_off[t >> 8][a] + (int)s_rank[t];
        if (pos < CCAP) {
            long long off = (long long)t * PLANE + a * CCAP + pos;
            __stcs(out + off, 1.0f);              // dispatch
            __stcs(out + HALF + off, g_gate[t]);  // combine
        }
    }

    // scalars + state reset for next graph replay
    if (tid == 0) {
        float aux = 0.f;
#pragma unroll
        for (int e = 0; e < E_EXP; e++) aux += g_psum[e] * (float)s_tot[e];
        const float invN = 1.0f / (float)N_TOK;
        out[2 * HALF]     = g_zsum * invN;                       // z_loss
        out[2 * HALF + 1] = aux * (float)E_EXP * invN * invN;    // aux_loss
        g_zsum = 0.f;
#pragma unroll
        for (int e = 0; e < E_EXP; e++) g_psum[e] = 0.f;
        __threadfence();
        g_done = 0;
    }
}

// ---------------- launch ----------------
extern "C" void kernel_launch(void* const* d_in, const int* in_sizes, int n_in,
                              void* d_out, int out_size) {
    const float* X  = (const float*)d_in[0];
    const float* Wg = (const float*)d_in[1];
    const float* bg = (const float*)d_in[2];
    float* out = (float*)d_out;

    // driver memset node: pure-write zero-fill of both output planes
    cudaMemsetAsync(out, 0, (size_t)(2 * HALF) * sizeof(float));

    k_pool<<<N_TOK, 512>>>(X, Wg, bg, out);  // pure-read + last-block finisher
}

// round 11
// speedup vs baseline: 1.0634x; 1.0442x over previous
#include <cuda_runtime.h>
#include <cstdint>

#define N_TOK   4096
#define C_DIM   64
#define HW      256
#define E_EXP   16
#define CCAP    384
#define PLANE   (E_EXP * CCAP)             /* 6144 */
#define HALF    ((long long)N_TOK * PLANE) /* 25,165,824 floats */
#define NBIN    32

// ---------------- device scratch (bins reset each replay by k_finish) -------------
__device__ float g_gate[N_TOK];
__device__ int   g_arg[N_TOK];
__device__ float g_psumb[NBIN * E_EXP];   // binned prob sums (bin-major)
__device__ float g_zsumb[NBIN];           // binned lse sums

// =====================================================================
// K1: pure-read pool. grid = 4096 x 512. No fences, no counters.
// =====================================================================
__global__ void __launch_bounds__(512, 4)
k_pool(const float* __restrict__ X, const float* __restrict__ Wg,
       const float* __restrict__ bg) {
    const int n    = blockIdx.x;
    const int tid  = threadIdx.x;
    const int w    = tid >> 5;
    const int lane = tid & 31;

    __shared__ float s_ch[C_DIM];
    __shared__ float s_w[C_DIM * E_EXP];

    for (int i = tid; i < C_DIM * E_EXP; i += 512) s_w[i] = Wg[i];

    // coalesced streaming read; warp w owns channels [4w, 4w+4)
    const float4* p = reinterpret_cast<const float4*>(X + (size_t)n * C_DIM * HW)
                      + w * 256;
    float part[4] = {0.f, 0.f, 0.f, 0.f};
#pragma unroll
    for (int k = 0; k < 8; k++) {
        float4 v = __ldcs(p + lane + 32 * k);       // lanes consecutive -> coalesced
        part[k >> 1] += (v.x + v.y) + (v.z + v.w);
    }
#pragma unroll
    for (int c = 0; c < 4; c++) {
        float s = part[c];
#pragma unroll
        for (int off = 16; off; off >>= 1) s += __shfl_xor_sync(0xffffffffu, s, off);
        if (lane == 0) s_ch[4 * w + c] = s * (1.0f / HW);
    }
    __syncthreads();

    if (w == 0) {
        float l = -INFINITY;
        if (lane < E_EXP) {
            float acc = bg[lane];
#pragma unroll
            for (int c = 0; c < C_DIM; c++) acc += s_ch[c] * s_w[c * E_EXP + lane];
            l = acc;
        }
        float mx = l;
#pragma unroll
        for (int off = 16; off; off >>= 1) mx = fmaxf(mx, __shfl_xor_sync(0xffffffffu, mx, off));
        float e = (lane < E_EXP) ? __expf(l - mx) : 0.f;
        float s = e;
#pragma unroll
        for (int off = 16; off; off >>= 1) s += __shfl_xor_sync(0xffffffffu, s, off);
        float prob = e / s;
        float lse  = mx + __logf(s);

        unsigned bal = __ballot_sync(0xffffffffu, l == mx);
        int arg = __ffs(bal) - 1;                   // lowest-index max == jnp argmax
        float gate = __shfl_sync(0xffffffffu, prob, arg);

        const int bin = n & (NBIN - 1);             // spread atomic contention 32x
        if (lane < E_EXP) atomicAdd(&g_psumb[bin * E_EXP + lane], prob);
        if (lane == 0) {
            g_gate[n] = gate;
            g_arg[n]  = arg;
            atomicAdd(&g_zsumb[bin], lse);
        }
    }
}

// =====================================================================
// K2: finish — bulk prefetch to shared, scan, scatter, scalars, reset.
// 1 block x 512. Kernel boundary orders it after memset + pool.
// =====================================================================
__global__ void __launch_bounds__(512)
k_finish(float* __restrict__ out) {
    __shared__ int            s_arg[N_TOK];    // 16 KB
    __shared__ float          s_gate[N_TOK];   // 16 KB
    __shared__ unsigned short s_rank[N_TOK];   //  8 KB
    __shared__ int   s_cnt[16][E_EXP + 1];
    __shared__ int   s_off[16][E_EXP + 1];
    __shared__ int   s_tot[E_EXP];
    __shared__ float s_psum[E_EXP];
    __shared__ float s_z;

    const int tid  = threadIdx.x;
    const int w    = tid >> 5;
    const int lane = tid & 31;

    // ---- phase 0: one bulk coalesced prefetch (all loads independent) ----
    {
        const int4*   pa = reinterpret_cast<const int4*>(g_arg);
        const float4* pg = reinterpret_cast<const float4*>(g_gate);
#pragma unroll
        for (int r = 0; r < 2; r++) {
            int i = tid + r * 512;                  // 1024 vec4 of each
            reinterpret_cast<int4*>(s_arg)[i]    = pa[i];
            reinterpret_cast<float4*>(s_gate)[i] = pg[i];
        }
        if (tid < E_EXP) s_psum[tid] = 0.f;
        if (tid == 0)    s_z = 0.f;
    }
    __syncthreads();

    // ---- phase A: per-chunk expert ranks (warp w owns tokens [256w, 256w+256)) ----
    if (lane <= E_EXP) s_cnt[w][lane] = 0;
    __syncwarp();
#pragma unroll
    for (int g = 0; g < 8; g++) {
        int n = 256 * w + 32 * g + lane;
        int a = s_arg[n];
        unsigned m = __match_any_sync(0xffffffffu, a);
        int prior = s_cnt[w][a];
        __syncwarp();
        if (lane == (int)__ffs(m) - 1) s_cnt[w][a] = prior + __popc(m);
        s_rank[n] = (unsigned short)(prior + __popc(m & ((1u << lane) - 1u)));
        __syncwarp();
    }
    __syncthreads();

    // ---- phase B: exclusive prefix over 16 chunks (warp w = expert w) ----
    if (lane < 16) {
        int v = s_cnt[lane][w];
        int x = v;
#pragma unroll
        for (int off = 1; off < 16; off <<= 1) {
            int y = __shfl_up_sync(0x0000ffffu, x, off);
            if (lane >= off) x += y;
        }
        s_off[lane][w] = x - v;
        if (lane == 15) s_tot[w] = x;
    }

    // ---- binned loss sums -> shared (and reset bins for next replay) ----
    {
        float v = g_psumb[tid];                     // 512 = NBIN*E_EXP exactly
        g_psumb[tid] = 0.f;
        atomicAdd(&s_psum[tid & (E_EXP - 1)], v);
        if (tid < NBIN) {
            float z = g_zsumb[tid];
            g_zsumb[tid] = 0.f;
            atomicAdd(&s_z, z);
        }
    }
    __syncthreads();

    // ---- phase C: positions + scatter nonzeros (all data in shared) ----
#pragma unroll
    for (int rep = 0; rep < 8; rep++) {
        int n = tid + rep * 512;
        int a = s_arg[n];
        int pos = s_off[n >> 8][a] + (int)s_rank[n];
        if (pos < CCAP) {
            long long off = (long long)n * PLANE + a * CCAP + pos;
            __stcs(out + off, 1.0f);              // dispatch
            __stcs(out + HALF + off, s_gate[n]);  // combine
        }
    }

    // ---- scalars ----
    if (tid == 0) {
        float aux = 0.f;
#pragma unroll
        for (int e = 0; e < E_EXP; e++) aux += s_psum[e] * (float)s_tot[e];
        const float invN = 1.0f / (float)N_TOK;
        out[2 * HALF]     = s_z * invN;                          // z_loss
        out[2 * HALF + 1] = aux * (float)E_EXP * invN * invN;    // aux_loss
    }
}

// ---------------- launch ----------------
extern "C" void kernel_launch(void* const* d_in, const int* in_sizes, int n_in,
                              void* d_out, int out_size) {
    const float* X  = (const float*)d_in[0];
    const float* Wg = (const float*)d_in[1];
    const float* bg = (const float*)d_in[2];
    float* out = (float*)d_out;

    // driver memset node: pure-write zero-fill of both output planes
    cudaMemsetAsync(out, 0, (size_t)(2 * HALF) * sizeof(float));

    k_pool<<<N_TOK, 512>>>(X, Wg, bg);   // pure-read stream, no fences
    k_finish<<<1, 512>>>(out);           // prefetch + scan + scatter + scalars
}

// round 12
// speedup vs baseline: 1.1248x; 1.0577x over previous
#include <cuda_runtime.h>
#include <cstdint>

#define N_TOK   4096
#define C_DIM   64
#define HW      256
#define E_EXP   16
#define CCAP    384
#define PLANE   (E_EXP * CCAP)             /* 6144 */
#define HALF    ((long long)N_TOK * PLANE) /* 25,165,824 floats */
#define NBIN    32

// ---------------- device scratch (bins reset each replay by k_finish blk 0) --------
__device__ float g_gate[N_TOK];
__device__ int   g_arg[N_TOK];
__device__ float g_psumb[NBIN * E_EXP];   // binned prob sums (bin-major)
__device__ float g_zsumb[NBIN];           // binned lse sums

// =====================================================================
// K1: pure-read pool. grid = 4096 x 512. No fences, no counters.
// =====================================================================
__global__ void __launch_bounds__(512, 4)
k_pool(const float* __restrict__ X, const float* __restrict__ Wg,
       const float* __restrict__ bg) {
    const int n    = blockIdx.x;
    const int tid  = threadIdx.x;
    const int w    = tid >> 5;
    const int lane = tid & 31;

    __shared__ float s_ch[C_DIM];
    __shared__ float s_w[C_DIM * E_EXP];

    for (int i = tid; i < C_DIM * E_EXP; i += 512) s_w[i] = Wg[i];

    // coalesced streaming read; warp w owns channels [4w, 4w+4)
    const float4* p = reinterpret_cast<const float4*>(X + (size_t)n * C_DIM * HW)
                      + w * 256;
    float part[4] = {0.f, 0.f, 0.f, 0.f};
#pragma unroll
    for (int k = 0; k < 8; k++) {
        float4 v = __ldcs(p + lane + 32 * k);       // lanes consecutive -> coalesced
        part[k >> 1] += (v.x + v.y) + (v.z + v.w);
    }
#pragma unroll
    for (int c = 0; c < 4; c++) {
        float s = part[c];
#pragma unroll
        for (int off = 16; off; off >>= 1) s += __shfl_xor_sync(0xffffffffu, s, off);
        if (lane == 0) s_ch[4 * w + c] = s * (1.0f / HW);
    }
    __syncthreads();

    if (w == 0) {
        float l = -INFINITY;
        if (lane < E_EXP) {
            float acc = bg[lane];
#pragma unroll
            for (int c = 0; c < C_DIM; c++) acc += s_ch[c] * s_w[c * E_EXP + lane];
            l = acc;
        }
        float mx = l;
#pragma unroll
        for (int off = 16; off; off >>= 1) mx = fmaxf(mx, __shfl_xor_sync(0xffffffffu, mx, off));
        float e = (lane < E_EXP) ? __expf(l - mx) : 0.f;
        float s = e;
#pragma unroll
        for (int off = 16; off; off >>= 1) s += __shfl_xor_sync(0xffffffffu, s, off);
        float prob = e / s;
        float lse  = mx + __logf(s);

        unsigned bal = __ballot_sync(0xffffffffu, l == mx);
        int arg = __ffs(bal) - 1;                   // lowest-index max == jnp argmax
        float gate = __shfl_sync(0xffffffffu, prob, arg);

        const int bin = n & (NBIN - 1);             // spread atomic contention 32x
        if (lane < E_EXP) atomicAdd(&g_psumb[bin * E_EXP + lane], prob);
        if (lane == 0) {
            g_gate[n] = gate;
            g_arg[n]  = arg;
            atomicAdd(&g_zsumb[bin], lse);
        }
    }
}

// =====================================================================
// K2: finish. grid = 32 x 512. Every block REPLICATES the cheap scan
// (L2-hot, no cross-block sync); block b scatters tokens [128b,128b+128),
// spreading the write-allocate store drain across 32 SMs. Block 0 also
// writes the scalars and resets the bins.
// =====================================================================
__global__ void __launch_bounds__(512)
k_finish(float* __restrict__ out) {
    __shared__ int            s_arg[N_TOK];    // 16 KB
    __shared__ unsigned short s_rank[N_TOK];   //  8 KB
    __shared__ int s_cnt[16][E_EXP + 1];
    __shared__ int s_off[16][E_EXP + 1];
    __shared__ int s_tot[E_EXP];

    const int bid  = blockIdx.x;
    const int tid  = threadIdx.x;
    const int w    = tid >> 5;
    const int lane = tid & 31;

    // phase 0: bulk coalesced prefetch of g_arg (L2-hot, read-only)
    {
        const int4* pa = reinterpret_cast<const int4*>(g_arg);
#pragma unroll
        for (int r = 0; r < 2; r++) {
            int i = tid + r * 512;
            reinterpret_cast<int4*>(s_arg)[i] = pa[i];
        }
    }
    __syncthreads();

    // phase A: per-chunk expert ranks (warp w owns tokens [256w, 256w+256))
    if (lane <= E_EXP) s_cnt[w][lane] = 0;
    __syncwarp();
#pragma unroll
    for (int g = 0; g < 8; g++) {
        int n = 256 * w + 32 * g + lane;
        int a = s_arg[n];
        unsigned m = __match_any_sync(0xffffffffu, a);
        int prior = s_cnt[w][a];
        __syncwarp();
        if (lane == (int)__ffs(m) - 1) s_cnt[w][a] = prior + __popc(m);
        s_rank[n] = (unsigned short)(prior + __popc(m & ((1u << lane) - 1u)));
        __syncwarp();
    }
    __syncthreads();

    // phase B: exclusive prefix over 16 chunks (warp w = expert w)
    if (lane < 16) {
        int v = s_cnt[lane][w];
        int x = v;
#pragma unroll
        for (int off = 1; off < 16; off <<= 1) {
            int y = __shfl_up_sync(0x0000ffffu, x, off);
            if (lane >= off) x += y;
        }
        s_off[lane][w] = x - v;
        if (lane == 15) s_tot[w] = x;
    }
    __syncthreads();

    // phase C: scatter THIS block's 128 tokens (one token per thread, tid<128)
    if (tid < 128) {
        int n   = 128 * bid + tid;
        int a   = s_arg[n];
        int pos = s_off[n >> 8][a] + (int)s_rank[n];
        if (pos < CCAP) {
            long long off = (long long)n * PLANE + a * CCAP + pos;
            float gate = g_gate[n];                 // L2-hit
            __stcs(out + off, 1.0f);                // dispatch
            __stcs(out + HALF + off, gate);         // combine
        }
    }

    // block 0: scalars + bin reset for next graph replay
    if (bid == 0) {
        __shared__ float s_psum[E_EXP];
        __shared__ float s_z;
        if (tid < E_EXP) s_psum[tid] = 0.f;
        if (tid == 0)    s_z = 0.f;
        __syncthreads();
        {
            float v = g_psumb[tid];                 // 512 = NBIN*E_EXP exactly
            g_psumb[tid] = 0.f;
            atomicAdd(&s_psum[tid & (E_EXP - 1)], v);
            if (tid < NBIN) {
                float z = g_zsumb[tid];
                g_zsumb[tid] = 0.f;
                atomicAdd(&s_z, z);
            }
        }
        __syncthreads();
        if (tid == 0) {
            float aux = 0.f;
#pragma unroll
            for (int e = 0; e < E_EXP; e++) aux += s_psum[e] * (float)s_tot[e];
            const float invN = 1.0f / (float)N_TOK;
            out[2 * HALF]     = s_z * invN;                        // z_loss
            out[2 * HALF + 1] = aux * (float)E_EXP * invN * invN;  // aux_loss
        }
    }
}

// ---------------- launch ----------------
extern "C" void kernel_launch(void* const* d_in, const int* in_sizes, int n_in,
                              void* d_out, int out_size) {
    const float* X  = (const float*)d_in[0];
    const float* Wg = (const float*)d_in[1];
    const float* bg = (const float*)d_in[2];
    float* out = (float*)d_out;

    // driver memset node: pure-write zero-fill of both output planes
    cudaMemsetAsync(out, 0, (size_t)(2 * HALF) * sizeof(float));

    k_pool<<<N_TOK, 512>>>(X, Wg, bg);   // pure-read stream, no fences
    k_finish<<<32, 512>>>(out);          // replicated scan + parallel scatter
}